// round 15
// baseline (speedup 1.0000x reference)
#include <cuda_runtime.h>
#include <cuda_fp16.h>

#define NN  50000
#define EE  800000
#define DIN 32
#define F   128      // HEADS * DIM_H
#define NPB 50       // nodes per block-group in transform phase
#define NG  (NN / NPB)   // 1000 transform groups
#define CAP 64       // padded bucket capacity (deg incl. self)
#define GRID 512
#define THREADS 256
#define NWARP (GRID * THREADS / 32)   // 4096 warps
#define NG2  (GRID * THREADS / 8)     // 16384 8-lane groups

// ---------------- scratch (device globals; no allocation allowed) ----------
__device__ __align__(16) __half g_xl1h[NN * F];   // fp16 gather table
__device__ __align__(16) __half g_xr1h[NN * F];   // fp16 dest table
__device__ float g_xl2[NN];
__device__ float g_xr2[NN];
__device__ __align__(16) int g_deg[NN];           // zeroed in phase C
__device__ __align__(16) int g_bkt[NN * CAP];     // padded per-dst edge lists
__device__ unsigned long long g_barA, g_barB;     // monotone epoch barriers

__device__ __forceinline__ float lrelu(float x) { return fmaxf(x, 0.2f * x); }

// ---- f32x2 packed helpers (Blackwell; PTX-only) ----------------------------
__device__ __forceinline__ unsigned long long pk2(float lo, float hi) {
    unsigned long long r;
    asm("mov.b64 %0, {%1, %2};" : "=l"(r) : "f"(lo), "f"(hi));
    return r;
}
__device__ __forceinline__ void upk2(unsigned long long v, float& lo, float& hi) {
    asm("mov.b64 {%0, %1}, %2;" : "=f"(lo), "=f"(hi) : "l"(v));
}
__device__ __forceinline__ unsigned long long fma2(
    unsigned long long a, unsigned long long b, unsigned long long c) {
    unsigned long long d;
    asm("fma.rn.f32x2 %0, %1, %2, %3;" : "=l"(d) : "l"(a), "l"(b), "l"(c));
    return d;
}

// Monotone epoch grid barrier: no resets, valid across all graph replays.
__device__ __forceinline__ void grid_barrier(unsigned long long* cnt) {
    __syncthreads();
    if (threadIdx.x == 0) {
        __threadfence();
        unsigned long long ticket = atomicAdd(cnt, 1ULL);
        unsigned long long target = (ticket / GRID + 1ULL) * GRID;
        volatile unsigned long long* vc = cnt;
        while (*vc < target) __nanosleep(64);
        __threadfence();
    }
    __syncthreads();
}

// ---------------- the whole pipeline in one persistent kernel ---------------
__global__ void __launch_bounds__(THREADS, 4) k_fused(
    const float* __restrict__ x,
    const int*   __restrict__ src,  const int* __restrict__ dst,
    const float* __restrict__ Wl1,  const float* __restrict__ bl1,
    const float* __restrict__ Wr1,  const float* __restrict__ br1,
    const float* __restrict__ att,  const float* __restrict__ bias,
    const float* __restrict__ Wl2,  const float* __restrict__ bl2,
    const float* __restrict__ Wr2,  const float* __restrict__ br2,
    const float* __restrict__ att2, const float* __restrict__ bias2,
    float* __restrict__ out)
{
    __shared__ float xs[NPB * DIN];
    int tid = threadIdx.x;
    int lane = tid & 31;

    // ======== phase A1: one-pass padded bucket build (int4, MLP 4) =========
    {
        int nchunk = (EE + NN) / 4;
        for (int t = blockIdx.x * THREADS + tid; t < nchunk; t += GRID * THREADS) {
            int base = t * 4;
            if (base < EE) {
                int4 s4 = ((const int4*)src)[t];
                int4 d4 = ((const int4*)dst)[t];
                int p0 = atomicAdd(&g_deg[d4.x], 1);
                int p1 = atomicAdd(&g_deg[d4.y], 1);
                int p2 = atomicAdd(&g_deg[d4.z], 1);
                int p3 = atomicAdd(&g_deg[d4.w], 1);
                if (p0 < CAP) g_bkt[d4.x * CAP + p0] = s4.x;
                if (p1 < CAP) g_bkt[d4.y * CAP + p1] = s4.y;
                if (p2 < CAP) g_bkt[d4.z * CAP + p2] = s4.z;
                if (p3 < CAP) g_bkt[d4.w * CAP + p3] = s4.w;
            } else {
#pragma unroll
                for (int j = 0; j < 4; j++) {
                    int d = base - EE + j;                 // self-loop
                    int pos = atomicAdd(&g_deg[d], 1);
                    if (pos < CAP) g_bkt[d * CAP + pos] = d;
                }
            }
        }
    }

    // ======== phase A2: node transforms (f32x2 packed FMA) =================
    {
        const float* W;
        int c;
        float b;
        if (tid < F) { W = Wl1; c = tid;     b = bl1[c]; }
        else         { W = Wr1; c = tid - F; b = br1[c]; }
        unsigned long long w2[DIN / 2];
#pragma unroll
        for (int k = 0; k < DIN / 2; k++)
            w2[k] = pk2(W[(2 * k) * F + c], W[(2 * k + 1) * F + c]);

        for (int g = blockIdx.x; g < NG; g += GRID) {
            int n0 = g * NPB;
            __syncthreads();
            for (int j = tid; j < NPB * DIN; j += THREADS) xs[j] = x[n0 * DIN + j];
            __syncthreads();
            const float2* xs2 = (const float2*)xs;
            for (int i = 0; i < NPB; i++) {
                unsigned long long acc = pk2(b, 0.f);
                const float2* xrow = xs2 + i * (DIN / 2);
#pragma unroll
                for (int k = 0; k < DIN / 2; k++) {
                    float2 xv = xrow[k];
                    acc = fma2(pk2(xv.x, xv.y), w2[k], acc);
                }
                float lo, hi;
                upk2(acc, lo, hi);
                float v = lo + hi;
                int node = n0 + i;
                if (tid < F) g_xl1h[node * F + c] = __float2half_rn(v);
                else         g_xr1h[node * F + c] = __float2half_rn(v);
            }
        }
    }

    grid_barrier(&g_barA);

    // ======== phase B: layer-1 aggregation (R11 warp-per-node) =============
    {
        int warp0 = (blockIdx.x * THREADS + tid) >> 5;
        const uint2* xlp = (const uint2*)g_xl1h;
        float4 at4 = ((const float4*)att)[lane];
        const __half2 c02 = __float2half2_rn(0.2f);

        for (int d = warp0; d < NN; d += NWARP) {
            uint2 xrr = ((const uint2*)g_xr1h)[d * 32 + lane];
            __half2 xr01 = *reinterpret_cast<__half2*>(&xrr.x);
            __half2 xr23 = *reinterpret_cast<__half2*>(&xrr.y);

            int deg = g_deg[d];
            if (deg > CAP) deg = CAP;
            const int* bkt = &g_bkt[d * CAP];

            float l = 0.f, ax = 0.f, ay = 0.f, az = 0.f, aw = 0.f;

#define AGG1_EDGE(r)                                                          \
    {                                                                         \
        __half2 h01 = *reinterpret_cast<__half2*>(&(r).x);                    \
        __half2 h23 = *reinterpret_cast<__half2*>(&(r).y);                    \
        __half2 v01 = __hadd2(h01, xr01);                                     \
        __half2 v23 = __hadd2(h23, xr23);                                     \
        __half2 t01 = __hmax2(v01, __hmul2(v01, c02));                        \
        __half2 t23 = __hmax2(v23, __hmul2(v23, c02));                        \
        float2 d01 = __half22float2(t01);                                     \
        float2 d23 = __half22float2(t23);                                     \
        float p = d01.x * at4.x;                                              \
        p = fmaf(d01.y, at4.y, p);                                            \
        p = fmaf(d23.x, at4.z, p);                                            \
        p = fmaf(d23.y, at4.w, p);                                            \
        p += __shfl_xor_sync(0xffffffffu, p, 1);                              \
        p += __shfl_xor_sync(0xffffffffu, p, 2);                              \
        float cc = __expf(p);                                                 \
        float2 f01 = __half22float2(h01);                                     \
        float2 f23 = __half22float2(h23);                                     \
        l += cc;                                                              \
        ax = fmaf(cc, f01.x, ax); ay = fmaf(cc, f01.y, ay);                   \
        az = fmaf(cc, f23.x, az); aw = fmaf(cc, f23.y, aw);                   \
    }

            int i = 0;
            for (; i + 4 <= deg; i += 4) {
                int4 s4 = *(const int4*)(bkt + i);
                uint2 ra = xlp[s4.x * 32 + lane];
                uint2 rb = xlp[s4.y * 32 + lane];
                uint2 rc = xlp[s4.z * 32 + lane];
                uint2 rd = xlp[s4.w * 32 + lane];
                AGG1_EDGE(ra) AGG1_EDGE(rb) AGG1_EDGE(rc) AGG1_EDGE(rd)
            }
            for (; i < deg; i++) {
                uint2 r = xlp[bkt[i] * 32 + lane];
                AGG1_EDGE(r)
            }
#undef AGG1_EDGE

            float inv = 1.f / l;
            float4 b4 = ((const float4*)bias)[lane];
            float h0 = ax * inv + b4.x; h0 = (h0 > 0.f) ? h0 : expm1f(h0);
            float h1 = ay * inv + b4.y; h1 = (h1 > 0.f) ? h1 : expm1f(h1);
            float h2 = az * inv + b4.z; h2 = (h2 > 0.f) ? h2 : expm1f(h2);
            float h3 = aw * inv + b4.w; h3 = (h3 > 0.f) ? h3 : expm1f(h3);

            float4 wl4 = ((const float4*)Wl2)[lane];
            float4 wr4 = ((const float4*)Wr2)[lane];
            float pl = h0 * wl4.x + h1 * wl4.y + h2 * wl4.z + h3 * wl4.w;
            float pr = h0 * wr4.x + h1 * wr4.y + h2 * wr4.z + h3 * wr4.w;
#pragma unroll
            for (int off = 16; off; off >>= 1) {
                pl += __shfl_xor_sync(0xffffffffu, pl, off);
                pr += __shfl_xor_sync(0xffffffffu, pr, off);
            }
            if (lane == 0) {
                g_xl2[d] = pl + bl2[0];
                g_xr2[d] = pr + br2[0];
            }
        }
    }

    grid_barrier(&g_barB);

    // ======== phase C: layer-2 aggregation (8 lanes/node) + deg reset ======
    {
        int grp0 = (blockIdx.x * THREADS + tid) >> 3;
        int sub = tid & 7;
        float a = att2[0];
        float bz = bias2[0];
        for (int w = grp0; w < NN; w += NG2) {
            float xr = g_xr2[w];
            int deg = g_deg[w];
            if (deg > CAP) deg = CAP;
            const int* bkt = &g_bkt[w * CAP];

            float den = 0.f, num = 0.f;
            for (int i = sub; i < deg; i += 8) {
                int s = bkt[i];
                float v = g_xl2[s];
                float c = __expf(a * lrelu(v + xr));
                den += c;
                num = fmaf(c, v, num);
            }
#pragma unroll
            for (int off = 4; off; off >>= 1) {
                den += __shfl_xor_sync(0xffffffffu, den, off);
                num += __shfl_xor_sync(0xffffffffu, num, off);
            }
            if (sub == 0) {
                out[w] = num / den + bz;
                g_deg[w] = 0;                 // clean state for next call
            }
        }
    }
}

// ---------------- launcher --------------------------------------------------
extern "C" void kernel_launch(void* const* d_in, const int* in_sizes, int n_in,
                              void* d_out, int out_size)
{
    const float* x     = (const float*)d_in[0];
    const int*   src   = (const int*)  d_in[1];
    const int*   dst   = (const int*)  d_in[2];
    const float* Wl1   = (const float*)d_in[3];
    const float* bl1   = (const float*)d_in[4];
    const float* Wr1   = (const float*)d_in[5];
    const float* br1   = (const float*)d_in[6];
    const float* att1  = (const float*)d_in[7];
    const float* bias1 = (const float*)d_in[8];
    const float* Wl2   = (const float*)d_in[9];
    const float* bl2   = (const float*)d_in[10];
    const float* Wr2   = (const float*)d_in[11];
    const float* br2   = (const float*)d_in[12];
    const float* att2  = (const float*)d_in[13];
    const float* bias2 = (const float*)d_in[14];
    float* out = (float*)d_out;

    k_fused<<<GRID, THREADS>>>(x, src, dst, Wl1, bl1, Wr1, br1,
                               att1, bias1, Wl2, bl2, Wr2, br2,
                               att2, bias2, out);
}

// round 16
// speedup vs baseline: 1.2953x; 1.2953x over previous
#include <cuda_runtime.h>
#include <cuda_fp16.h>

#define NN  50000
#define EE  800000
#define DIN 32
#define F   128      // HEADS * DIM_H
#define NPB 50       // nodes per block in transform1
#define CAP 64       // padded bucket capacity (deg incl. self; P(>=64) ~ 1e-17)

// ---------------- scratch (device globals; no allocation allowed) ----------
__device__ __align__(16) __half g_xl1h[NN * F];   // fp16 gather table
__device__ __align__(16) __half g_xr1h[NN * F];   // fp16 dest table
__device__ float g_xl2[NN];
__device__ float g_xr2[NN];
__device__ __align__(16) int g_deg[NN];           // zeroed by k_agg2 epilogue
__device__ __align__(16) int g_bkt[NN * CAP];     // padded per-dst edge lists

__device__ __forceinline__ float lrelu(float x) { return fmaxf(x, 0.2f * x); }

// ---- f32x2 packed helpers (Blackwell; PTX-only) ----------------------------
__device__ __forceinline__ unsigned long long pk2(float lo, float hi) {
    unsigned long long r;
    asm("mov.b64 %0, {%1, %2};" : "=l"(r) : "f"(lo), "f"(hi));
    return r;
}
__device__ __forceinline__ void upk2(unsigned long long v, float& lo, float& hi) {
    asm("mov.b64 {%0, %1}, %2;" : "=f"(lo), "=f"(hi) : "l"(v));
}
__device__ __forceinline__ unsigned long long fma2(
    unsigned long long a, unsigned long long b, unsigned long long c) {
    unsigned long long d;
    asm("fma.rn.f32x2 %0, %1, %2, %3;" : "=l"(d) : "l"(a), "l"(b), "l"(c));
    return d;
}

// ---------------- one-pass padded-CSR build: 4 items/thread (MLP 4) ---------
__global__ void k_build(const int* __restrict__ src, const int* __restrict__ dst) {
    int t = blockIdx.x * blockDim.x + threadIdx.x;
    if (t >= (EE + NN) / 4) return;
    int base = t * 4;
    if (base < EE) {
        int4 s4 = ((const int4*)src)[t];
        int4 d4 = ((const int4*)dst)[t];
        int p0 = atomicAdd(&g_deg[d4.x], 1);
        int p1 = atomicAdd(&g_deg[d4.y], 1);
        int p2 = atomicAdd(&g_deg[d4.z], 1);
        int p3 = atomicAdd(&g_deg[d4.w], 1);
        if (p0 < CAP) g_bkt[d4.x * CAP + p0] = s4.x;
        if (p1 < CAP) g_bkt[d4.y * CAP + p1] = s4.y;
        if (p2 < CAP) g_bkt[d4.z * CAP + p2] = s4.z;
        if (p3 < CAP) g_bkt[d4.w * CAP + p3] = s4.w;
    } else {
#pragma unroll
        for (int j = 0; j < 4; j++) {
            int d = base - EE + j;                 // self-loop
            int pos = atomicAdd(&g_deg[d], 1);
            if (pos < CAP) g_bkt[d * CAP + pos] = d;
        }
    }
}

// ---------------- layer-1 node transforms: f32x2 packed FMA -----------------
__global__ void __launch_bounds__(256) k_transform1(
    const float* __restrict__ x,
    const float* __restrict__ Wl, const float* __restrict__ bl,
    const float* __restrict__ Wr, const float* __restrict__ br)
{
    __shared__ float xs[NPB * DIN];
    int t = threadIdx.x;
    const float* W;
    int c;
    float b;
    if (t < F) { W = Wl; c = t;     b = bl[c]; }
    else       { W = Wr; c = t - F; b = br[c]; }

    unsigned long long w2[DIN / 2];
#pragma unroll
    for (int k = 0; k < DIN / 2; k++)
        w2[k] = pk2(W[(2 * k) * F + c], W[(2 * k + 1) * F + c]);

    int n0 = blockIdx.x * NPB;
    for (int j = t; j < NPB * DIN; j += 256) xs[j] = x[n0 * DIN + j];
    __syncthreads();

    const float2* xs2 = (const float2*)xs;
    for (int i = 0; i < NPB; i++) {
        unsigned long long acc = pk2(b, 0.f);
        const float2* xrow = xs2 + i * (DIN / 2);
#pragma unroll
        for (int k = 0; k < DIN / 2; k++) {
            float2 xv = xrow[k];
            acc = fma2(pk2(xv.x, xv.y), w2[k], acc);
        }
        float lo, hi;
        upk2(acc, lo, hi);
        float v = lo + hi;
        int node = n0 + i;
        if (t < F) g_xl1h[node * F + c] = __float2half_rn(v);
        else       g_xr1h[node * F + c] = __float2half_rn(v);
    }
}

// ---------------- layer-1 aggregation: R11 layout, half2 logit dot ----------
// Warp per node, lane = 4 contiguous channels (uint2). The logit dot runs in
// half2 (hadd2/hmul2/hmax2/hfma2) with ONE float2 convert per edge; weighted
// accumulation stays fp32. Identical gather/index pattern to R11.
__global__ void __launch_bounds__(256) k_agg1(
    const float* __restrict__ att,  const float* __restrict__ bias,
    const float* __restrict__ Wl2, const float* __restrict__ bl2,
    const float* __restrict__ Wr2, const float* __restrict__ br2)
{
    int w = (blockIdx.x * 256 + threadIdx.x) >> 5;
    if (w >= NN) return;
    int lane = threadIdx.x & 31;
    int d = w;

    const uint2* xlp = (const uint2*)g_xl1h;
    uint2 xrr = ((const uint2*)g_xr1h)[d * 32 + lane];
    __half2 xr01 = *reinterpret_cast<__half2*>(&xrr.x);
    __half2 xr23 = *reinterpret_cast<__half2*>(&xrr.y);
    float4 at4 = ((const float4*)att)[lane];
    __half2 ah01 = __floats2half2_rn(at4.x, at4.y);
    __half2 ah23 = __floats2half2_rn(at4.z, at4.w);
    const __half2 c02 = __float2half2_rn(0.2f);

    int deg = g_deg[d];
    if (deg > CAP) deg = CAP;
    const int* bkt = &g_bkt[d * CAP];

    float l = 0.f, ax = 0.f, ay = 0.f, az = 0.f, aw = 0.f;

#define AGG1_EDGE(r)                                                          \
    {                                                                         \
        __half2 h01 = *reinterpret_cast<__half2*>(&(r).x);                    \
        __half2 h23 = *reinterpret_cast<__half2*>(&(r).y);                    \
        __half2 v01 = __hadd2(h01, xr01);                                     \
        __half2 v23 = __hadd2(h23, xr23);                                     \
        __half2 t01 = __hmax2(v01, __hmul2(v01, c02));                        \
        __half2 t23 = __hmax2(v23, __hmul2(v23, c02));                        \
        __half2 pacc = __hfma2(t01, ah01, __hmul2(t23, ah23));                \
        float2 pf = __half22float2(pacc);                                     \
        float p = pf.x + pf.y;                                                \
        p += __shfl_xor_sync(0xffffffffu, p, 1);                              \
        p += __shfl_xor_sync(0xffffffffu, p, 2);                              \
        float cc = __expf(p);                                                 \
        float2 f01 = __half22float2(h01);                                     \
        float2 f23 = __half22float2(h23);                                     \
        l += cc;                                                              \
        ax = fmaf(cc, f01.x, ax); ay = fmaf(cc, f01.y, ay);                   \
        az = fmaf(cc, f23.x, az); aw = fmaf(cc, f23.y, aw);                   \
    }

    int i = 0;
    for (; i + 4 <= deg; i += 4) {
        int4 s4 = *(const int4*)(bkt + i);
        uint2 ra = xlp[s4.x * 32 + lane];
        uint2 rb = xlp[s4.y * 32 + lane];
        uint2 rc = xlp[s4.z * 32 + lane];
        uint2 rd = xlp[s4.w * 32 + lane];
        AGG1_EDGE(ra) AGG1_EDGE(rb) AGG1_EDGE(rc) AGG1_EDGE(rd)
    }
    for (; i < deg; i++) {
        uint2 r = xlp[bkt[i] * 32 + lane];
        AGG1_EDGE(r)
    }
#undef AGG1_EDGE

    float inv = 1.f / l;
    float4 b4 = ((const float4*)bias)[lane];
    float h0 = ax * inv + b4.x; h0 = (h0 > 0.f) ? h0 : expm1f(h0);
    float h1 = ay * inv + b4.y; h1 = (h1 > 0.f) ? h1 : expm1f(h1);
    float h2 = az * inv + b4.z; h2 = (h2 > 0.f) ? h2 : expm1f(h2);
    float h3 = aw * inv + b4.w; h3 = (h3 > 0.f) ? h3 : expm1f(h3);

    float4 wl4 = ((const float4*)Wl2)[lane];
    float4 wr4 = ((const float4*)Wr2)[lane];
    float pl = h0 * wl4.x + h1 * wl4.y + h2 * wl4.z + h3 * wl4.w;
    float pr = h0 * wr4.x + h1 * wr4.y + h2 * wr4.z + h3 * wr4.w;
#pragma unroll
    for (int off = 16; off; off >>= 1) {
        pl += __shfl_xor_sync(0xffffffffu, pl, off);
        pr += __shfl_xor_sync(0xffffffffu, pr, off);
    }
    if (lane == 0) {
        g_xl2[d] = pl + bl2[0];
        g_xr2[d] = pr + br2[0];
    }
}

// ---------------- layer-2 aggregation: 8 lanes per node ---------------------
// Also zeroes g_deg (last consumer) so the next call starts clean.
__global__ void __launch_bounds__(256) k_agg2(
    const float* __restrict__ att2, const float* __restrict__ bias2,
    float* __restrict__ out)
{
    int gid = blockIdx.x * 256 + threadIdx.x;
    int w = gid >> 3;                 // 8 lanes per node, groups warp-aligned
    if (w >= NN) return;
    int sub = gid & 7;

    float xr = g_xr2[w];
    float a = att2[0];
    int deg = g_deg[w];
    if (deg > CAP) deg = CAP;
    const int* bkt = &g_bkt[w * CAP];

    float den = 0.f, num = 0.f;
    for (int i = sub; i < deg; i += 8) {
        int s = bkt[i];
        float v = g_xl2[s];
        float c = __expf(a * lrelu(v + xr));
        den += c;
        num = fmaf(c, v, num);
    }
#pragma unroll
    for (int off = 4; off; off >>= 1) {
        den += __shfl_xor_sync(0xffffffffu, den, off);
        num += __shfl_xor_sync(0xffffffffu, num, off);
    }
    if (sub == 0) {
        out[w] = num / den + bias2[0];
        g_deg[w] = 0;                 // clean state for next call
    }
}

// ---------------- launcher --------------------------------------------------
extern "C" void kernel_launch(void* const* d_in, const int* in_sizes, int n_in,
                              void* d_out, int out_size)
{
    const float* x     = (const float*)d_in[0];
    const int*   src   = (const int*)  d_in[1];
    const int*   dst   = (const int*)  d_in[2];
    const float* Wl1   = (const float*)d_in[3];
    const float* bl1   = (const float*)d_in[4];
    const float* Wr1   = (const float*)d_in[5];
    const float* br1   = (const float*)d_in[6];
    const float* att1  = (const float*)d_in[7];
    const float* bias1 = (const float*)d_in[8];
    const float* Wl2   = (const float*)d_in[9];
    const float* bl2   = (const float*)d_in[10];
    const float* Wr2   = (const float*)d_in[11];
    const float* br2   = (const float*)d_in[12];
    const float* att2  = (const float*)d_in[13];
    const float* bias2 = (const float*)d_in[14];
    float* out = (float*)d_out;

    static cudaStream_t s2 = nullptr;
    static cudaEvent_t evFork = nullptr, evJoin = nullptr;
    if (!s2) {
        cudaStreamCreateWithFlags(&s2, cudaStreamNonBlocking);
        cudaEventCreateWithFlags(&evFork, cudaEventDisableTiming);
        cudaEventCreateWithFlags(&evJoin, cudaEventDisableTiming);
    }

    // fork: transform1 runs concurrently with the one-pass bucket build
    cudaEventRecord(evFork, 0);
    cudaStreamWaitEvent(s2, evFork, 0);
    k_transform1<<<NN / NPB, 256, 0, s2>>>(x, Wl1, bl1, Wr1, br1);
    cudaEventRecord(evJoin, s2);

    k_build<<<((EE + NN) / 4 + 255) / 256, 256>>>(src, dst);

    // join, then aggregation
    cudaStreamWaitEvent(0, evJoin, 0);
    k_agg1<<<NN / 8, 256>>>(att1, bias1, Wl2, bl2, Wr2, br2);
    k_agg2<<<(NN * 8 + 255) / 256, 256>>>(att2, bias2, out);
}